// round 1
// baseline (speedup 1.0000x reference)
#include <cuda_runtime.h>
#include <math.h>

#define B_ 4
#define M_ 2048
#define E_ 1024
#define D_ 256
#define H_ 8
#define DH_ 32
#define SPLITK 4
#define KCH (M_ / SPLITK)   // 512

// ---------------- scratch (device globals: allocation-free) ----------------
__device__ float g_q[B_*H_*M_*DH_];        // 8 MB
__device__ float g_k[B_*H_*M_*DH_];
__device__ float g_v[B_*H_*M_*DH_];
__device__ float g_attn[B_*M_*D_];         // 8 MB
__device__ float g_attnout[B_*M_*D_];
__device__ float g_Spart[SPLITK*B_*E_*D_]; // 16 MB
__device__ float g_S[B_*E_*D_];            // 4 MB
__device__ float g_ef[B_*E_*D_];
__device__ float g_ef2[B_*E_*D_];

// ---------------- NT GEMM: C[M,N] = A[M,K] @ B[N,K]^T (+bias) --------------
// 128x128 tile, BK=8, 256 threads, 8x8 micro-tile.
// EPI==0: plain store to C. EPI==1: scatter into g_q/g_k/g_v [b,h,m,dh].
template<int EPI>
__global__ __launch_bounds__(256, 2)
void gemm_nt(const float* __restrict__ A, const float* __restrict__ Bw,
             const float* __restrict__ bias, float* __restrict__ C,
             int M, int N, int K)
{
    __shared__ float As[8][128];
    __shared__ float Bs[8][128];
    const int t  = threadIdx.x;
    const int m0 = blockIdx.y * 128, n0 = blockIdx.x * 128;
    const int lr = t >> 1;
    const int lk = (t & 1) * 4;
    const float* Ag = A  + (size_t)(m0 + lr) * K + lk;
    const float* Bg = Bw + (size_t)(n0 + lr) * K + lk;
    const int tx = t & 15, ty = t >> 4;

    float acc[8][8];
#pragma unroll
    for (int i = 0; i < 8; i++)
#pragma unroll
        for (int j = 0; j < 8; j++) acc[i][j] = 0.f;

    for (int k0 = 0; k0 < K; k0 += 8) {
        float4 av = *(const float4*)(Ag + k0);
        float4 bv = *(const float4*)(Bg + k0);
        As[lk+0][lr] = av.x; As[lk+1][lr] = av.y;
        As[lk+2][lr] = av.z; As[lk+3][lr] = av.w;
        Bs[lk+0][lr] = bv.x; Bs[lk+1][lr] = bv.y;
        Bs[lk+2][lr] = bv.z; Bs[lk+3][lr] = bv.w;
        __syncthreads();
#pragma unroll
        for (int kk = 0; kk < 8; kk++) {
            float4 a0 = *(const float4*)&As[kk][ty*8];
            float4 a1 = *(const float4*)&As[kk][ty*8+4];
            float4 b0 = *(const float4*)&Bs[kk][tx*8];
            float4 b1 = *(const float4*)&Bs[kk][tx*8+4];
            float a[8] = {a0.x,a0.y,a0.z,a0.w,a1.x,a1.y,a1.z,a1.w};
            float b[8] = {b0.x,b0.y,b0.z,b0.w,b1.x,b1.y,b1.z,b1.w};
#pragma unroll
            for (int i = 0; i < 8; i++)
#pragma unroll
                for (int j = 0; j < 8; j++) acc[i][j] += a[i]*b[j];
        }
        __syncthreads();
    }

    float bb[8];
#pragma unroll
    for (int j = 0; j < 8; j++) bb[j] = bias ? bias[n0 + tx*8 + j] : 0.f;

    if (EPI == 0) {
#pragma unroll
        for (int i = 0; i < 8; i++) {
            float* Cp = C + (size_t)(m0 + ty*8 + i) * N + n0 + tx*8;
            *(float4*)Cp     = make_float4(acc[i][0]+bb[0], acc[i][1]+bb[1],
                                           acc[i][2]+bb[2], acc[i][3]+bb[3]);
            *(float4*)(Cp+4) = make_float4(acc[i][4]+bb[4], acc[i][5]+bb[5],
                                           acc[i][6]+bb[6], acc[i][7]+bb[7]);
        }
    } else {
        // qkv scatter: col n in [0,768): which=n/256, dd=n%256, h=dd/32, c=dd%32
#pragma unroll
        for (int i = 0; i < 8; i++) {
            int m  = m0 + ty*8 + i;
            int bi = m >> 11, mm = m & (M_-1);
#pragma unroll
            for (int jg = 0; jg < 8; jg += 4) {
                int n = n0 + tx*8 + jg;
                int which = n >> 8;
                int dd = n & 255;
                int h = dd >> 5, c = dd & 31;
                float* dst = (which == 0 ? g_q : which == 1 ? g_k : g_v)
                           + (size_t)(((bi << 3) + h) * M_ + mm) * DH_ + c;
                *(float4*)dst = make_float4(acc[i][jg]+bb[jg],   acc[i][jg+1]+bb[jg+1],
                                            acc[i][jg+2]+bb[jg+2], acc[i][jg+3]+bb[jg+3]);
            }
        }
    }
}

// ---------------- TN GEMM (split-K): S_partial = inc[b]^T @ attnout[b] -----
// A = inc[b]   [M_=2048 x E_=1024] (e contiguous)
// B = attnout[b] [2048 x 256]      (d contiguous)
// grid: (D tiles=2, E tiles=8, B_*SPLITK=16)
__global__ __launch_bounds__(256, 2)
void gemm_tn_S(const float* __restrict__ inc)
{
    __shared__ float As[8][128];  // [k][e]
    __shared__ float Bs[8][128];  // [k][d]
    const int t  = threadIdx.x;
    const int z  = blockIdx.z;
    const int b  = z >> 2, sk = z & 3;
    const int e0 = blockIdx.y * 128, d0 = blockIdx.x * 128;
    const int kbase = sk * KCH;
    const float* Ag = inc       + (size_t)b * M_ * E_;
    const float* Bg = g_attnout + (size_t)b * M_ * D_;
    const int kr = t >> 5, cc = (t & 31) * 4;
    const int tx = t & 15, ty = t >> 4;

    float acc[8][8];
#pragma unroll
    for (int i = 0; i < 8; i++)
#pragma unroll
        for (int j = 0; j < 8; j++) acc[i][j] = 0.f;

    for (int k0 = 0; k0 < KCH; k0 += 8) {
        int krow = kbase + k0 + kr;
        *(float4*)&As[kr][cc] = *(const float4*)(Ag + (size_t)krow * E_ + e0 + cc);
        *(float4*)&Bs[kr][cc] = *(const float4*)(Bg + (size_t)krow * D_ + d0 + cc);
        __syncthreads();
#pragma unroll
        for (int kk = 0; kk < 8; kk++) {
            float4 a0 = *(const float4*)&As[kk][ty*8];
            float4 a1 = *(const float4*)&As[kk][ty*8+4];
            float4 b0 = *(const float4*)&Bs[kk][tx*8];
            float4 b1 = *(const float4*)&Bs[kk][tx*8+4];
            float a[8] = {a0.x,a0.y,a0.z,a0.w,a1.x,a1.y,a1.z,a1.w};
            float b[8] = {b0.x,b0.y,b0.z,b0.w,b1.x,b1.y,b1.z,b1.w};
#pragma unroll
            for (int i = 0; i < 8; i++)
#pragma unroll
                for (int j = 0; j < 8; j++) acc[i][j] += a[i]*b[j];
        }
        __syncthreads();
    }

    float* Cp = g_Spart + (size_t)(sk * B_ + b) * E_ * D_;
#pragma unroll
    for (int i = 0; i < 8; i++) {
        float* p = Cp + (size_t)(e0 + ty*8 + i) * D_ + d0 + tx*8;
        *(float4*)p     = make_float4(acc[i][0], acc[i][1], acc[i][2], acc[i][3]);
        *(float4*)(p+4) = make_float4(acc[i][4], acc[i][5], acc[i][6], acc[i][7]);
    }
}

// deterministic split-K reduction
__global__ void reduce_S()
{
    const int i = blockIdx.x * 256 + threadIdx.x;          // float4 index
    const int N4 = B_*E_*D_/4;                             // 262144
    const float4* p = (const float4*)g_Spart;
    float4 a = p[i], b = p[i + N4], c = p[i + 2*N4], d = p[i + 3*N4];
    ((float4*)g_S)[i] = make_float4(a.x+b.x+c.x+d.x, a.y+b.y+c.y+d.y,
                                    a.z+b.z+c.z+d.z, a.w+b.w+c.w+d.w);
}

// ---------------- flash attention (fp32, lane = query) ---------------------
// grid: (M_/128=16, B_*H_=32), block 128 (4 warps, 32 queries each)
#define TK 16
__global__ __launch_bounds__(128, 4)
void flash_attn()
{
    __shared__ float Ks[TK][32];
    __shared__ float Vs[TK][32];
    const int bh   = blockIdx.y;           // b*8+h
    const int t    = threadIdx.x;
    const int lane = t & 31, wid = t >> 5;
    const int q    = blockIdx.x * 128 + wid * 32 + lane;

    const float scale = 0.17677669529663687f;   // 1/sqrt(32)
    const float* qp = g_q + ((size_t)bh * M_ + q) * DH_;
    float qr[32];
#pragma unroll
    for (int c = 0; c < 32; c += 4) {
        float4 v = *(const float4*)(qp + c);
        qr[c] = v.x*scale; qr[c+1] = v.y*scale; qr[c+2] = v.z*scale; qr[c+3] = v.w*scale;
    }
    float o[32];
#pragma unroll
    for (int c = 0; c < 32; c++) o[c] = 0.f;
    float mrun = -1e30f, lrun = 0.f;

    const float* kb = g_k + (size_t)bh * M_ * DH_;
    const float* vb = g_v + (size_t)bh * M_ * DH_;
    const int jj = t >> 3;          // 0..15 row
    const int cc = (t & 7) * 4;     // 0..28

    for (int kt = 0; kt < M_; kt += TK) {
        *(float4*)&Ks[jj][cc] = *(const float4*)(kb + (size_t)(kt + jj)*DH_ + cc);
        *(float4*)&Vs[jj][cc] = *(const float4*)(vb + (size_t)(kt + jj)*DH_ + cc);
        __syncthreads();

        float s[TK];
#pragma unroll
        for (int j = 0; j < TK; j++) {
            float acc = 0.f;
#pragma unroll
            for (int c = 0; c < 32; c += 4) {
                float4 kv = *(const float4*)&Ks[j][c];
                acc += qr[c]*kv.x; acc += qr[c+1]*kv.y;
                acc += qr[c+2]*kv.z; acc += qr[c+3]*kv.w;
            }
            s[j] = acc;
        }
        float tmax = s[0];
#pragma unroll
        for (int j = 1; j < TK; j++) tmax = fmaxf(tmax, s[j]);
        float mnew = fmaxf(mrun, tmax);
        float corr = __expf(mrun - mnew);
        lrun *= corr;
#pragma unroll
        for (int c = 0; c < 32; c++) o[c] *= corr;
#pragma unroll
        for (int j = 0; j < TK; j++) {
            float p = __expf(s[j] - mnew);
            lrun += p;
#pragma unroll
            for (int c = 0; c < 32; c += 4) {
                float4 vv = *(const float4*)&Vs[j][c];
                o[c]   += p*vv.x; o[c+1] += p*vv.y;
                o[c+2] += p*vv.z; o[c+3] += p*vv.w;
            }
        }
        mrun = mnew;
        __syncthreads();
    }

    float inv = 1.f / lrun;
    const int b = bh >> 3, h = bh & 7;
    float* op = g_attn + ((size_t)b * M_ + q) * D_ + h * DH_;
#pragma unroll
    for (int c = 0; c < 32; c += 4)
        *(float4*)(op + c) = make_float4(o[c]*inv, o[c+1]*inv, o[c+2]*inv, o[c+3]*inv);
}

// ---------------- softmax over hyperedge dim + ef = S*W --------------------
// one warp per (b,d) column; 1024 columns; grid 128, block 256
__global__ void softmax_e()
{
    const int t = threadIdx.x, lane = t & 31, wid = t >> 5;
    const int col = blockIdx.x * 8 + wid;       // 0..1023
    const int b = col >> 8, d = col & 255;
    const float* base = g_S + (size_t)b * E_ * D_ + d;
    float v[32];
    float mx = -1e30f;
#pragma unroll
    for (int r = 0; r < 32; r++) {
        float x = base[(size_t)(lane + r*32) * D_];
        v[r] = x; mx = fmaxf(mx, x);
    }
#pragma unroll
    for (int off = 16; off; off >>= 1) mx = fmaxf(mx, __shfl_xor_sync(~0u, mx, off));
    float se = 0.f;
#pragma unroll
    for (int r = 0; r < 32; r++) se += __expf(v[r] - mx);
#pragma unroll
    for (int off = 16; off; off >>= 1) se += __shfl_xor_sync(~0u, se, off);
    float inv = 1.f / se;
    float* ob = g_ef + (size_t)b * E_ * D_ + d;
#pragma unroll
    for (int r = 0; r < 32; r++)
        ob[(size_t)(lane + r*32) * D_] = v[r] * __expf(v[r] - mx) * inv;
}

// ---------------- LayerNorm + residual -------------------------------------
// one warp per row (D_=256 -> 8 elems/lane); rows = B_*E_ = 4096; grid 512
__global__ void ln_residual(const float* __restrict__ prev,
                            const float* __restrict__ gamma,
                            const float* __restrict__ beta,
                            const float* __restrict__ alphap,
                            float* __restrict__ out)
{
    const int t = threadIdx.x, lane = t & 31, wid = t >> 5;
    const int row = blockIdx.x * 8 + wid;
    const float* x = g_ef2 + (size_t)row * D_;
    float xs[8], sum = 0.f, sq = 0.f;
#pragma unroll
    for (int c = 0; c < 8; c++) {
        float v = x[lane + c*32];
        xs[c] = v; sum += v; sq += v*v;
    }
#pragma unroll
    for (int off = 16; off; off >>= 1) {
        sum += __shfl_xor_sync(~0u, sum, off);
        sq  += __shfl_xor_sync(~0u, sq,  off);
    }
    const float mu   = sum * (1.f / D_);
    const float var  = sq * (1.f / D_) - mu * mu;
    const float rstd = rsqrtf(var + 1e-5f);
    const float alpha = *alphap;
#pragma unroll
    for (int c = 0; c < 8; c++) {
        int d = lane + c*32;
        float y = (xs[c] - mu) * rstd * gamma[d] + beta[d];
        size_t idx = (size_t)row * D_ + d;
        out[idx] = (1.f + alpha) * prev[idx] + (1.f - alpha) * y;
    }
}

// ---------------- launch ----------------------------------------------------
extern "C" void kernel_launch(void* const* d_in, const int* in_sizes, int n_in,
                              void* d_out, int out_size)
{
    const float* feature = (const float*)d_in[0];
    const float* inc     = (const float*)d_in[1];
    const float* prev    = (const float*)d_in[2];
    const float* inw     = (const float*)d_in[3];
    const float* inb     = (const float*)d_in[4];
    const float* outw    = (const float*)d_in[5];
    const float* outb    = (const float*)d_in[6];
    const float* projw   = (const float*)d_in[7];
    const float* gamma   = (const float*)d_in[8];
    const float* beta    = (const float*)d_in[9];
    const float* alphap  = (const float*)d_in[10];
    float* out = (float*)d_out;

    float *p_attn = 0, *p_attnout = 0, *p_ef = 0, *p_ef2 = 0;
    cudaGetSymbolAddress((void**)&p_attn,    g_attn);
    cudaGetSymbolAddress((void**)&p_attnout, g_attnout);
    cudaGetSymbolAddress((void**)&p_ef,      g_ef);
    cudaGetSymbolAddress((void**)&p_ef2,     g_ef2);

    // 1. QKV projection: [8192,256] @ [768,256]^T -> scatter to q/k/v
    gemm_nt<1><<<dim3(6, 64), 256>>>(feature, inw, inb, (float*)0, B_*M_, 3*D_, D_);
    // 2. attention
    flash_attn<<<dim3(16, 32), 128>>>();
    // 3. out_proj: [8192,256] @ [256,256]^T + bias
    gemm_nt<0><<<dim3(2, 64), 256>>>(p_attn, outw, outb, p_attnout, B_*M_, D_, D_);
    // 4. S = inc^T @ attnout (split-K partials) + reduce
    gemm_tn_S<<<dim3(2, 8, B_*SPLITK), 256>>>(inc);
    reduce_S<<<B_*E_*D_/4/256, 256>>>();
    // 5. softmax over e + ef = S*W
    softmax_e<<<128, 256>>>();
    // 6. projection: [4096,256] @ [256,256]^T
    gemm_nt<0><<<dim3(2, 32), 256>>>(p_ef, projw, (float*)0, p_ef2, B_*E_, D_, D_);
    // 7. LN + residual mix
    ln_residual<<<512, 256>>>(prev, gamma, beta, alphap, out);
}

// round 2
// speedup vs baseline: 2.8317x; 2.8317x over previous
#include <cuda_runtime.h>
#include <math.h>

#define B_ 4
#define M_ 2048
#define E_ 1024
#define D_ 256
#define H_ 8
#define DH_ 32
#define SPLITK 4
#define KCH (M_ / SPLITK)   // 512

// ---------------- scratch (device globals: allocation-free) ----------------
__device__ float g_q[B_*H_*M_*DH_];
__device__ float g_k[B_*H_*M_*DH_];
__device__ float g_v[B_*H_*M_*DH_];
__device__ float g_attn[B_*M_*D_];
__device__ float g_attnout[B_*M_*D_];
__device__ float g_Spart[SPLITK*B_*E_*D_];
__device__ float g_S[B_*E_*D_];
__device__ float g_ef[B_*E_*D_];
__device__ float g_ef2[B_*E_*D_];

// ---------------- tf32 helpers ---------------------------------------------
__device__ __forceinline__ unsigned f2tf(float f) {
    unsigned u;
    asm("cvt.rna.tf32.f32 %0, %1;" : "=r"(u) : "f"(f));
    return u;
}
// D += A@B, m16n8k8 tf32
__device__ __forceinline__ void mma8(float* d, const unsigned* a, const unsigned* b) {
    asm volatile(
        "mma.sync.aligned.m16n8k8.row.col.f32.tf32.tf32.f32 "
        "{%0,%1,%2,%3},{%4,%5,%6,%7},{%8,%9},{%0,%1,%2,%3};"
        : "+f"(d[0]), "+f"(d[1]), "+f"(d[2]), "+f"(d[3])
        : "r"(a[0]), "r"(a[1]), "r"(a[2]), "r"(a[3]), "r"(b[0]), "r"(b[1]));
}

// ---------------- NT tf32 GEMM: C[M,N] = A[M,K] @ Bw[N,K]^T (+bias) --------
// 128x128x32 tile, 256 thr (8 warps 2x4), warp tile 64x32 (4 m-tiles, 4 n-tiles)
// EPI==0: plain store. EPI==1: scatter into g_q/g_k/g_v [bh,m,dh].
template<int EPI>
__global__ __launch_bounds__(256, 2)
void gemm_nt_tf32(const float* __restrict__ A, const float* __restrict__ Bw,
                  const float* __restrict__ bias, float* __restrict__ C,
                  int M, int N, int K)
{
    __shared__ unsigned As[128][36];   // [m][k] row-major, pad 4
    __shared__ unsigned Bs[128][36];   // [n][k] row-major, pad 4
    const int t = threadIdx.x, lane = t & 31, w = t >> 5;
    const int m0 = blockIdx.y * 128, n0 = blockIdx.x * 128;
    const int wm = (w & 1) * 64, wn = (w >> 1) * 32;
    const int g = lane >> 2, qt = lane & 3;

    float acc[4][4][4];
#pragma unroll
    for (int i = 0; i < 4; i++)
#pragma unroll
        for (int j = 0; j < 4; j++)
#pragma unroll
            for (int r = 0; r < 4; r++) acc[i][j][r] = 0.f;

    for (int k0 = 0; k0 < K; k0 += 32) {
#pragma unroll
        for (int p = 0; p < 4; p++) {
            int linear = p * 1024 + t * 4;
            int r = linear >> 5, c = linear & 31;
            float4 av = *(const float4*)(A + (size_t)(m0 + r) * K + k0 + c);
            As[r][c] = f2tf(av.x); As[r][c+1] = f2tf(av.y);
            As[r][c+2] = f2tf(av.z); As[r][c+3] = f2tf(av.w);
            float4 bv = *(const float4*)(Bw + (size_t)(n0 + r) * K + k0 + c);
            Bs[r][c] = f2tf(bv.x); Bs[r][c+1] = f2tf(bv.y);
            Bs[r][c+2] = f2tf(bv.z); Bs[r][c+3] = f2tf(bv.w);
        }
        __syncthreads();
#pragma unroll
        for (int ks = 0; ks < 4; ks++) {
            unsigned af[4][4], bf[4][2];
            const int kc = ks * 8 + qt;
#pragma unroll
            for (int mt = 0; mt < 4; mt++) {
                const int mr = wm + mt * 16 + g;
                af[mt][0] = As[mr][kc];     af[mt][1] = As[mr+8][kc];
                af[mt][2] = As[mr][kc+4];   af[mt][3] = As[mr+8][kc+4];
            }
#pragma unroll
            for (int nt = 0; nt < 4; nt++) {
                const int nr = wn + nt * 8 + g;
                bf[nt][0] = Bs[nr][kc];     bf[nt][1] = Bs[nr][kc+4];
            }
#pragma unroll
            for (int mt = 0; mt < 4; mt++)
#pragma unroll
                for (int nt = 0; nt < 4; nt++)
                    mma8(acc[mt][nt], af[mt], bf[nt]);
        }
        __syncthreads();
    }

    // epilogue: thread owns rows (g, g+8) per m-tile, col pairs (2qt, 2qt+1) per n-tile
#pragma unroll
    for (int mt = 0; mt < 4; mt++) {
#pragma unroll
        for (int nt = 0; nt < 4; nt++) {
            const int n = n0 + wn + nt * 8 + 2 * qt;
            float b0 = bias ? bias[n] : 0.f;
            float b1 = bias ? bias[n+1] : 0.f;
#pragma unroll
            for (int rh = 0; rh < 2; rh++) {
                const int m = m0 + wm + mt * 16 + g + rh * 8;
                float v0 = acc[mt][nt][rh*2] + b0;
                float v1 = acc[mt][nt][rh*2+1] + b1;
                if (EPI == 0) {
                    *(float2*)(C + (size_t)m * N + n) = make_float2(v0, v1);
                } else {
                    int bi = m >> 11, mm = m & (M_ - 1);
                    int which = n >> 8, dd = n & 255;
                    int h = dd >> 5, c = dd & 31;
                    float* dst = (which == 0 ? g_q : which == 1 ? g_k : g_v)
                               + (size_t)(((bi << 3) + h) * M_ + mm) * DH_ + c;
                    *(float2*)dst = make_float2(v0, v1);
                }
            }
        }
    }
}

// ---------------- TN tf32 GEMM (split-K): S_partial = inc^T @ attnout ------
// output rows = e (1024), cols = d (256), reduction over tokens m.
// native layouts are already [k][m]/[k][n]: straight float4 copies, no transpose.
__global__ __launch_bounds__(256, 2)
void gemm_tn_S_tf32(const float* __restrict__ inc)
{
    __shared__ unsigned As[32][132];   // [token][e], pad 4
    __shared__ unsigned Bs[32][132];   // [token][d], pad 4
    const int t = threadIdx.x, lane = t & 31, w = t >> 5;
    const int z = blockIdx.z;
    const int b = z >> 2, sk = z & 3;
    const int e0 = blockIdx.y * 128, d0 = blockIdx.x * 128;
    const int kbase = sk * KCH;
    const int wm = (w & 1) * 64, wn = (w >> 1) * 32;
    const int g = lane >> 2, qt = lane & 3;
    const float* Ag = inc       + (size_t)b * M_ * E_;
    const float* Bg = g_attnout + (size_t)b * M_ * D_;

    float acc[4][4][4];
#pragma unroll
    for (int i = 0; i < 4; i++)
#pragma unroll
        for (int j = 0; j < 4; j++)
#pragma unroll
            for (int r = 0; r < 4; r++) acc[i][j][r] = 0.f;

    for (int k0 = 0; k0 < KCH; k0 += 32) {
#pragma unroll
        for (int p = 0; p < 4; p++) {
            int linear = p * 1024 + t * 4;
            int r = linear >> 7, c = linear & 127;
            int krow = kbase + k0 + r;
            float4 av = *(const float4*)(Ag + (size_t)krow * E_ + e0 + c);
            As[r][c] = f2tf(av.x); As[r][c+1] = f2tf(av.y);
            As[r][c+2] = f2tf(av.z); As[r][c+3] = f2tf(av.w);
            float4 bv = *(const float4*)(Bg + (size_t)krow * D_ + d0 + c);
            Bs[r][c] = f2tf(bv.x); Bs[r][c+1] = f2tf(bv.y);
            Bs[r][c+2] = f2tf(bv.z); Bs[r][c+3] = f2tf(bv.w);
        }
        __syncthreads();
#pragma unroll
        for (int ks = 0; ks < 4; ks++) {
            unsigned af[4][4], bf[4][2];
            const int kc = ks * 8 + qt;
#pragma unroll
            for (int mt = 0; mt < 4; mt++) {
                const int mr = wm + mt * 16 + g;
                af[mt][0] = As[kc][mr];     af[mt][1] = As[kc][mr+8];
                af[mt][2] = As[kc+4][mr];   af[mt][3] = As[kc+4][mr+8];
            }
#pragma unroll
            for (int nt = 0; nt < 4; nt++) {
                const int nr = wn + nt * 8 + g;
                bf[nt][0] = Bs[kc][nr];     bf[nt][1] = Bs[kc+4][nr];
            }
#pragma unroll
            for (int mt = 0; mt < 4; mt++)
#pragma unroll
                for (int nt = 0; nt < 4; nt++)
                    mma8(acc[mt][nt], af[mt], bf[nt]);
        }
        __syncthreads();
    }

    float* Cp = g_Spart + (size_t)(sk * B_ + b) * E_ * D_;
#pragma unroll
    for (int mt = 0; mt < 4; mt++)
#pragma unroll
        for (int nt = 0; nt < 4; nt++) {
            const int d = d0 + wn + nt * 8 + 2 * qt;
#pragma unroll
            for (int rh = 0; rh < 2; rh++) {
                const int e = e0 + wm + mt * 16 + g + rh * 8;
                *(float2*)(Cp + (size_t)e * D_ + d) =
                    make_float2(acc[mt][nt][rh*2], acc[mt][nt][rh*2+1]);
            }
        }
}

// deterministic split-K reduction
__global__ void reduce_S()
{
    const int i = blockIdx.x * 256 + threadIdx.x;
    const int N4 = B_*E_*D_/4;
    const float4* p = (const float4*)g_Spart;
    float4 a = p[i], b = p[i + N4], c = p[i + 2*N4], d = p[i + 3*N4];
    ((float4*)g_S)[i] = make_float4(a.x+b.x+c.x+d.x, a.y+b.y+c.y+d.y,
                                    a.z+b.z+c.z+d.z, a.w+b.w+c.w+d.w);
}

// ---------------- tensor-core flash attention (tf32 mma) -------------------
// grid (16 q-tiles, 32 bh), block 128 (4 warps). Warp owns 32 q rows.
// Per iter: K/V tile of 64 keys in smem; S=Q@K^T via mma; fragment softmax;
// P through warp-private padded smem; O += P@V via mma.
#define FTK 64
#define KV_STRIDE 36
#define P_STRIDE 68
#define FLASH_SMEM ((2*FTK*KV_STRIDE + 4*32*P_STRIDE) * 4)

__global__ __launch_bounds__(128, 2)
void flash_attn_tf32()
{
    extern __shared__ unsigned smem[];
    unsigned* Ks = smem;                        // [64][36]
    unsigned* Vs = Ks + FTK * KV_STRIDE;        // [64][36]
    unsigned* Psw;                              // per-warp [32][68]

    const int t = threadIdx.x, lane = t & 31, w = t >> 5;
    const int g = lane >> 2, qt = lane & 3;
    const int bh = blockIdx.y;
    const int qbase = blockIdx.x * 128 + w * 32;
    Psw = Vs + FTK * KV_STRIDE + w * 32 * P_STRIDE;

    const float scale = 0.17677669529663687f;   // 1/sqrt(32)
    const float* qp = g_q + ((size_t)bh * M_ + qbase) * DH_;

    unsigned qf[2][4][4];
#pragma unroll
    for (int mt = 0; mt < 2; mt++)
#pragma unroll
        for (int ks = 0; ks < 4; ks++) {
            int r0 = mt * 16 + g, c0 = ks * 8 + qt;
            qf[mt][ks][0] = f2tf(scale * qp[r0*32 + c0]);
            qf[mt][ks][1] = f2tf(scale * qp[(r0+8)*32 + c0]);
            qf[mt][ks][2] = f2tf(scale * qp[r0*32 + c0 + 4]);
            qf[mt][ks][3] = f2tf(scale * qp[(r0+8)*32 + c0 + 4]);
        }

    float of[2][4][4];
#pragma unroll
    for (int i = 0; i < 2; i++)
#pragma unroll
        for (int j = 0; j < 4; j++)
#pragma unroll
            for (int r = 0; r < 4; r++) of[i][j][r] = 0.f;
    float mr[2][2] = {{-1e30f,-1e30f},{-1e30f,-1e30f}};
    float lr[2][2] = {{0.f,0.f},{0.f,0.f}};

    const float* kb = g_k + (size_t)bh * M_ * DH_;
    const float* vb = g_v + (size_t)bh * M_ * DH_;

    for (int kt = 0; kt < M_; kt += FTK) {
        __syncthreads();
#pragma unroll
        for (int p = 0; p < 4; p++) {
            int linear = p * 512 + t * 4;
            int r = linear >> 5, c = linear & 31;
            float4 kv = *(const float4*)(kb + (size_t)(kt + r) * DH_ + c);
            Ks[r*KV_STRIDE + c]   = f2tf(kv.x); Ks[r*KV_STRIDE + c+1] = f2tf(kv.y);
            Ks[r*KV_STRIDE + c+2] = f2tf(kv.z); Ks[r*KV_STRIDE + c+3] = f2tf(kv.w);
            float4 vv = *(const float4*)(vb + (size_t)(kt + r) * DH_ + c);
            Vs[r*KV_STRIDE + c]   = f2tf(vv.x); Vs[r*KV_STRIDE + c+1] = f2tf(vv.y);
            Vs[r*KV_STRIDE + c+2] = f2tf(vv.z); Vs[r*KV_STRIDE + c+3] = f2tf(vv.w);
        }
        __syncthreads();

        // S = Q @ K^T  (per warp: 32q x 64keys)
        float sf[2][8][4];
#pragma unroll
        for (int i = 0; i < 2; i++)
#pragma unroll
            for (int j = 0; j < 8; j++)
#pragma unroll
                for (int r = 0; r < 4; r++) sf[i][j][r] = 0.f;
#pragma unroll
        for (int ks = 0; ks < 4; ks++) {
            unsigned bf[8][2];
            const int kc = ks * 8 + qt;
#pragma unroll
            for (int n = 0; n < 8; n++) {
                bf[n][0] = Ks[(n*8 + g)*KV_STRIDE + kc];
                bf[n][1] = Ks[(n*8 + g)*KV_STRIDE + kc + 4];
            }
#pragma unroll
            for (int mt = 0; mt < 2; mt++)
#pragma unroll
                for (int n = 0; n < 8; n++)
                    mma8(sf[mt][n], qf[mt][ks], bf[n]);
        }

        // online softmax on fragments; P -> warp-private smem (tf32)
#pragma unroll
        for (int mt = 0; mt < 2; mt++) {
#pragma unroll
            for (int rh = 0; rh < 2; rh++) {
                float mx = -1e30f;
#pragma unroll
                for (int n = 0; n < 8; n++) {
                    mx = fmaxf(mx, sf[mt][n][rh*2]);
                    mx = fmaxf(mx, sf[mt][n][rh*2+1]);
                }
                mx = fmaxf(mx, __shfl_xor_sync(~0u, mx, 1));
                mx = fmaxf(mx, __shfl_xor_sync(~0u, mx, 2));
                float mn = fmaxf(mr[mt][rh], mx);
                float corr = __expf(mr[mt][rh] - mn);
                mr[mt][rh] = mn;
                lr[mt][rh] *= corr;
#pragma unroll
                for (int nd = 0; nd < 4; nd++) {
                    of[mt][nd][rh*2]   *= corr;
                    of[mt][nd][rh*2+1] *= corr;
                }
                float ls = 0.f;
                const int prow = (mt*16 + g + rh*8) * P_STRIDE;
#pragma unroll
                for (int n = 0; n < 8; n++) {
                    float e0 = __expf(sf[mt][n][rh*2]   - mn);
                    float e1 = __expf(sf[mt][n][rh*2+1] - mn);
                    ls += e0 + e1;
                    Psw[prow + n*8 + 2*qt]     = f2tf(e0);
                    Psw[prow + n*8 + 2*qt + 1] = f2tf(e1);
                }
                lr[mt][rh] += ls;
            }
        }
        __syncwarp();

        // O += P @ V  (32q x 64k @ 64k x 32d)
#pragma unroll
        for (int ks = 0; ks < 8; ks++) {
            unsigned af[2][4], bf[4][2];
            const int kc = ks * 8 + qt;
#pragma unroll
            for (int mt = 0; mt < 2; mt++) {
                const int r0 = (mt*16 + g) * P_STRIDE;
                af[mt][0] = Psw[r0 + kc];
                af[mt][1] = Psw[r0 + 8*P_STRIDE + kc];
                af[mt][2] = Psw[r0 + kc + 4];
                af[mt][3] = Psw[r0 + 8*P_STRIDE + kc + 4];
            }
#pragma unroll
            for (int nd = 0; nd < 4; nd++) {
                bf[nd][0] = Vs[kc*KV_STRIDE + nd*8 + g];
                bf[nd][1] = Vs[(kc+4)*KV_STRIDE + nd*8 + g];
            }
#pragma unroll
            for (int mt = 0; mt < 2; mt++)
#pragma unroll
                for (int nd = 0; nd < 4; nd++)
                    mma8(of[mt][nd], af[mt], bf[nd]);
        }
    }

    // finalize + store into g_attn [b][m][h*32 + d]
    const int b = bh >> 3, h = bh & 7;
#pragma unroll
    for (int mt = 0; mt < 2; mt++)
#pragma unroll
        for (int rh = 0; rh < 2; rh++) {
            float l = lr[mt][rh];
            l += __shfl_xor_sync(~0u, l, 1);
            l += __shfl_xor_sync(~0u, l, 2);
            float inv = 1.f / l;
            const int q = qbase + mt*16 + g + rh*8;
            float* op = g_attn + ((size_t)b * M_ + q) * D_ + h * DH_;
#pragma unroll
            for (int nd = 0; nd < 4; nd++)
                *(float2*)(op + nd*8 + 2*qt) =
                    make_float2(of[mt][nd][rh*2]*inv, of[mt][nd][rh*2+1]*inv);
        }
}

// ---------------- softmax over hyperedge dim + ef = S*W --------------------
__global__ void softmax_e()
{
    const int t = threadIdx.x, lane = t & 31, wid = t >> 5;
    const int col = blockIdx.x * 8 + wid;
    const int b = col >> 8, d = col & 255;
    const float* base = g_S + (size_t)b * E_ * D_ + d;
    float v[32];
    float mx = -1e30f;
#pragma unroll
    for (int r = 0; r < 32; r++) {
        float x = base[(size_t)(lane + r*32) * D_];
        v[r] = x; mx = fmaxf(mx, x);
    }
#pragma unroll
    for (int off = 16; off; off >>= 1) mx = fmaxf(mx, __shfl_xor_sync(~0u, mx, off));
    float se = 0.f;
#pragma unroll
    for (int r = 0; r < 32; r++) se += __expf(v[r] - mx);
#pragma unroll
    for (int off = 16; off; off >>= 1) se += __shfl_xor_sync(~0u, se, off);
    float inv = 1.f / se;
    float* ob = g_ef + (size_t)b * E_ * D_ + d;
#pragma unroll
    for (int r = 0; r < 32; r++)
        ob[(size_t)(lane + r*32) * D_] = v[r] * __expf(v[r] - mx) * inv;
}

// ---------------- LayerNorm + residual -------------------------------------
__global__ void ln_residual(const float* __restrict__ prev,
                            const float* __restrict__ gamma,
                            const float* __restrict__ beta,
                            const float* __restrict__ alphap,
                            float* __restrict__ out)
{
    const int t = threadIdx.x, lane = t & 31, wid = t >> 5;
    const int row = blockIdx.x * 8 + wid;
    const float* x = g_ef2 + (size_t)row * D_;
    float xs[8], sum = 0.f, sq = 0.f;
#pragma unroll
    for (int c = 0; c < 8; c++) {
        float v = x[lane + c*32];
        xs[c] = v; sum += v; sq += v*v;
    }
#pragma unroll
    for (int off = 16; off; off >>= 1) {
        sum += __shfl_xor_sync(~0u, sum, off);
        sq  += __shfl_xor_sync(~0u, sq,  off);
    }
    const float mu   = sum * (1.f / D_);
    const float var  = sq * (1.f / D_) - mu * mu;
    const float rstd = rsqrtf(var + 1e-5f);
    const float alpha = *alphap;
#pragma unroll
    for (int c = 0; c < 8; c++) {
        int d = lane + c*32;
        float y = (xs[c] - mu) * rstd * gamma[d] + beta[d];
        size_t idx = (size_t)row * D_ + d;
        out[idx] = (1.f + alpha) * prev[idx] + (1.f - alpha) * y;
    }
}

// ---------------- launch ----------------------------------------------------
extern "C" void kernel_launch(void* const* d_in, const int* in_sizes, int n_in,
                              void* d_out, int out_size)
{
    const float* feature = (const float*)d_in[0];
    const float* inc     = (const float*)d_in[1];
    const float* prev    = (const float*)d_in[2];
    const float* inw     = (const float*)d_in[3];
    const float* inb     = (const float*)d_in[4];
    const float* outw    = (const float*)d_in[5];
    const float* outb    = (const float*)d_in[6];
    const float* projw   = (const float*)d_in[7];
    const float* gamma   = (const float*)d_in[8];
    const float* beta    = (const float*)d_in[9];
    const float* alphap  = (const float*)d_in[10];
    float* out = (float*)d_out;

    float *p_attn = 0, *p_attnout = 0, *p_ef = 0, *p_ef2 = 0;
    cudaGetSymbolAddress((void**)&p_attn,    g_attn);
    cudaGetSymbolAddress((void**)&p_attnout, g_attnout);
    cudaGetSymbolAddress((void**)&p_ef,      g_ef);
    cudaGetSymbolAddress((void**)&p_ef2,     g_ef2);

    cudaFuncSetAttribute(flash_attn_tf32,
                         cudaFuncAttributeMaxDynamicSharedMemorySize, FLASH_SMEM);

    // 1. QKV projection -> scatter to q/k/v
    gemm_nt_tf32<1><<<dim3(6, 64), 256>>>(feature, inw, inb, (float*)0, B_*M_, 3*D_, D_);
    // 2. attention (tensor cores)
    flash_attn_tf32<<<dim3(16, 32), 128, FLASH_SMEM>>>();
    // 3. out_proj
    gemm_nt_tf32<0><<<dim3(2, 64), 256>>>(p_attn, outw, outb, p_attnout, B_*M_, D_, D_);
    // 4. S = inc^T @ attnout (split-K) + reduce
    gemm_tn_S_tf32<<<dim3(2, 8, B_*SPLITK), 256>>>(inc);
    reduce_S<<<B_*E_*D_/4/256, 256>>>();
    // 5. softmax over e + ef = S*W
    softmax_e<<<128, 256>>>();
    // 6. final projection
    gemm_nt_tf32<0><<<dim3(2, 32), 256>>>(p_ef, projw, (float*)0, p_ef2, B_*E_, D_, D_);
    // 7. LN + residual mix
    ln_residual<<<512, 256>>>(prev, gamma, beta, alphap, out);
}